// round 1
// baseline (speedup 1.0000x reference)
#include <cuda_runtime.h>

// CompressKV: y[b,m,h,d] = (sum_k x[b, m*16+k, h, d]*w[k] + sum_k pe[k,d]*w[k]) / 32
// Shapes: x (4,16384,8,128) f32, w (32) f32, pe (32,128) f32, y (4,1023,8,128) f32.

#define CB 4
#define CN 16384
#define CH 8
#define CD 128
#define CK 32
#define CSTRIDE 16
#define CM 1023          // (16384 - 32)/16 + 1
#define MCHUNK 8

__global__ __launch_bounds__(256, 2)
void compresskv_kernel(const float4* __restrict__ x,
                       const float*  __restrict__ w,
                       const float4* __restrict__ pe,
                       float4*       __restrict__ y)
{
    const int d4 = threadIdx.x & 31;        // float4 lane within 128-float row
    const int j  = threadIdx.x >> 5;        // local m within chunk
    const int m  = blockIdx.x * MCHUNK + j;
    if (m >= CM) return;
    const int h = blockIdx.y;
    const int b = blockIdx.z;

    // weights (broadcast loads; compiler hoists into registers)
    float wk[CK];
#pragma unroll
    for (int k = 0; k < CK; ++k) wk[k] = __ldg(&w[k]);

    const int ROW4 = CH * (CD / 4);         // float4 stride between consecutive n: 256
    const float4* xp = x + ((size_t)((b * CN + m * CSTRIDE) * CH + h)) * (CD / 4) + d4;

    float ax = 0.f, ay = 0.f, az = 0.f, aw = 0.f;
#pragma unroll
    for (int k = 0; k < CK; ++k) {
        float4 v = __ldg(&xp[(size_t)k * ROW4]);
        ax = fmaf(wk[k], v.x, ax);
        ay = fmaf(wk[k], v.y, ay);
        az = fmaf(wk[k], v.z, az);
        aw = fmaf(wk[k], v.w, aw);
    }

    // bias: sum_k pe[k][d] * w[k]  (pe is 16 KB — L1/L2 resident)
#pragma unroll
    for (int k = 0; k < CK; ++k) {
        float4 p = __ldg(&pe[k * (CD / 4) + d4]);
        ax = fmaf(wk[k], p.x, ax);
        ay = fmaf(wk[k], p.y, ay);
        az = fmaf(wk[k], p.z, az);
        aw = fmaf(wk[k], p.w, aw);
    }

    const float s = 1.0f / (float)CK;
    float4 out;
    out.x = ax * s; out.y = ay * s; out.z = az * s; out.w = aw * s;
    y[((size_t)((b * CM + m) * CH + h)) * (CD / 4) + d4] = out;
}

extern "C" void kernel_launch(void* const* d_in, const int* in_sizes, int n_in,
                              void* d_out, int out_size)
{
    const float4* x  = (const float4*)d_in[0];
    const float*  w  = (const float*) d_in[1];
    const float4* pe = (const float4*)d_in[2];
    float4*       y  = (float4*)d_out;

    dim3 grid((CM + MCHUNK - 1) / MCHUNK, CH, CB);   // (128, 8, 4)
    dim3 block(256);
    compresskv_kernel<<<grid, block>>>(x, w, pe, y);
}